// round 10
// baseline (speedup 1.0000x reference)
#include <cuda_runtime.h>

#define BATCH   128
#define NN      100
#define DD      128
#define ITILE   20          // i-rows per CTA (100/20 = 5 tiles per batch)
#define NTILES  5
#define PITCH   132         // PITCH/4 == 33 ≡ 1 (mod 8): consecutive rows -> distinct quad-bank groups
#define THREADS 256
#define MASKV   (-9e15f)
#define NEG_BIG (-3.4e38f)

// smem (floats): Hs 100*132 | At 3*132 | Bt 9*132 | sA 20*100 | sB 20*100
#define SMEM_FLOATS (NN*PITCH + 3*PITCH + 9*PITCH + 2*ITILE*NN)
#define SMEM_BYTES  (SMEM_FLOATS * 4)

typedef unsigned long long u64t;

// packed fp32x2 helpers (sm_100+): 2 IEEE fp32 ops per instruction
__device__ __forceinline__ u64t mul2(u64t a, u64t b) {
    u64t r;
    asm("mul.rn.f32x2 %0, %1, %2;" : "=l"(r) : "l"(a), "l"(b));
    return r;
}
__device__ __forceinline__ void fma2(u64t& acc, u64t a, u64t b) {
    asm("fma.rn.f32x2 %0, %1, %2, %0;" : "+l"(acc) : "l"(a), "l"(b));
}
__device__ __forceinline__ u64t dup2(float f) {
    u64t r;
    asm("mov.b64 %0, {%1, %1};" : "=l"(r) : "f"(f));
    return r;
}
__device__ __forceinline__ float hsum2(u64t v) {
    float lo, hi;
    asm("mov.b64 {%0, %1}, %2;" : "=f"(lo), "=f"(hi) : "l"(v));
    return lo + hi;
}

extern "C" __global__ void __launch_bounds__(THREADS, 2)
la_kernel(const float* __restrict__ hidden,
          const int*   __restrict__ adj,
          const int*   __restrict__ beh,
          const float* __restrict__ A,
          const float* __restrict__ Bm,
          float*       __restrict__ out)
{
    extern __shared__ float smem[];
    float* Hs = smem;
    float* At = Hs + NN*PITCH;
    float* Bt = At + 3*PITCH;
    float* sA = Bt + 9*PITCH;
    float* sB = sA + ITILE*NN;

    const int tid = threadIdx.x;
    const int b   = blockIdx.x / NTILES;
    const int i0  = (blockIdx.x % NTILES) * ITILE;

    // ---- stage hidden[b] (pitched, float4) ----
    {
        const float4* hg = (const float4*)(hidden + (size_t)b * NN * DD);
        for (int v = tid; v < NN * (DD/4); v += THREADS) {
            int j = v >> 5;                       // DD/4 == 32
            int qq = v & 31;
            *(float4*)&Hs[j * PITCH + qq * 4] = hg[j * (DD/4) + qq];
        }
    }
    // ---- stage A,Bm transposed ----
    for (int t = tid; t < DD*3; t += THREADS) {
        int d = t / 3, k = t - d*3;
        At[k * PITCH + d] = A[t];
    }
    for (int t = tid; t < DD*9; t += THREADS) {
        int d = t / 9, k = t - d*9;
        Bt[k * PITCH + d] = Bm[t];
    }
    __syncthreads();

    // ---- score phase: 2i x 4j per thread, dense-A (3 ch) + gathered-B, f32x2 math ----
    if (tid < 250) {
        const int p = tid / 25;                   // i-group 0..9
        const int q = tid - p * 25;               // j-group 0..24
        const int* adjB = adj + (size_t)b * NN * NN;
        const int* behB = beh + (size_t)b * NN * NN;

        unsigned iaPack = 0, vaPack = 0, vbPack = 0;
        const float* bp[2][4];
        #pragma unroll
        for (int t = 0; t < 2; t++) {
            int i = i0 + p + 10*t;
            #pragma unroll
            for (int s = 0; s < 4; s++) {
                int j  = q + 25*s;
                int ca = adjB[i * NN + j];
                int cb = behB[i * NN + j];
                int ia = min(max(ca - 1, 0), 2);
                int ib = min(max(cb - 1, 0), 8);
                int k  = t*4 + s;
                iaPack |= (unsigned)ia << (2*k);
                vaPack |= (unsigned)((ca >= 1) & (ca <= 3)) << k;
                vbPack |= (unsigned)(cb >= 1) << k;
                bp[t][s] = &Bt[ib * PITCH];
            }
        }
        const float* hiP0 = &Hs[(i0 + p)      * PITCH];
        const float* hiP1 = &Hs[(i0 + p + 10) * PITCH];

        u64t a0c[2][4], a1c[2][4], a2c[2][4], bAc[2][4];
        #pragma unroll
        for (int t = 0; t < 2; t++)
            #pragma unroll
            for (int s = 0; s < 4; s++)
                a0c[t][s] = a1c[t][s] = a2c[t][s] = bAc[t][s] = 0ull;

        #pragma unroll 1
        for (int d = 0; d < DD; d += 4) {
            ulonglong2 w0 = *(const ulonglong2*)&At[d];             // broadcast
            ulonglong2 w1 = *(const ulonglong2*)&At[PITCH   + d];
            ulonglong2 w2 = *(const ulonglong2*)&At[2*PITCH + d];
            ulonglong2 hi[2], hj[4];
            hi[0] = *(const ulonglong2*)(hiP0 + d);
            hi[1] = *(const ulonglong2*)(hiP1 + d);
            #pragma unroll
            for (int s = 0; s < 4; s++)
                hj[s] = *(const ulonglong2*)&Hs[(q + 25*s) * PITCH + d];
            #pragma unroll
            for (int t = 0; t < 2; t++) {
                #pragma unroll
                for (int s = 0; s < 4; s++) {
                    ulonglong2 bv = *(const ulonglong2*)(bp[t][s] + d); // gather (9 rows)
                    u64t plo = mul2(hi[t].x, hj[s].x);
                    u64t phi = mul2(hi[t].y, hj[s].y);
                    fma2(a0c[t][s], plo, w0.x); fma2(a0c[t][s], phi, w0.y);
                    fma2(a1c[t][s], plo, w1.x); fma2(a1c[t][s], phi, w1.y);
                    fma2(a2c[t][s], plo, w2.x); fma2(a2c[t][s], phi, w2.y);
                    fma2(bAc[t][s], plo, bv.x); fma2(bAc[t][s], phi, bv.y);
                }
            }
        }

        #pragma unroll
        for (int t = 0; t < 2; t++) {
            int il = p + 10*t;
            #pragma unroll
            for (int s = 0; s < 4; s++) {
                int j = q + 25*s;
                int k = t*4 + s;
                int ia = (iaPack >> (2*k)) & 3;
                u64t sel = (ia == 0) ? a0c[t][s] : (ia == 1) ? a1c[t][s] : a2c[t][s];
                float va = hsum2(sel);
                float vb = hsum2(bAc[t][s]);
                va = va >= 0.f ? va : 0.2f * va;       // LeakyReLU(0.2)
                vb = vb >= 0.f ? vb : 0.2f * vb;
                sA[il * NN + j] = ((vaPack >> k) & 1) ? va : MASKV;
                sB[il * NN + j] = ((vbPack >> k) & 1) ? vb : MASKV;
            }
        }
    }
    __syncthreads();

    // ---- dual softmax + combine: W[j] = 0.5*pA[j] + 0.5*pB[j] (into sA) ----
    {
        int w = tid >> 5, lane = tid & 31;
        for (int r = w; r < ITILE; r += THREADS/32) {
            float* rowA = &sA[r * NN];
            float* rowB = &sB[r * NN];
            float va[4], vb[4];
            float mA = NEG_BIG, mB = NEG_BIG;
            #pragma unroll
            for (int u = 0; u < 4; u++) {
                int j = lane + 32*u;
                va[u] = (j < NN) ? rowA[j] : NEG_BIG;
                vb[u] = (j < NN) ? rowB[j] : NEG_BIG;
                mA = fmaxf(mA, va[u]);
                mB = fmaxf(mB, vb[u]);
            }
            #pragma unroll
            for (int o = 16; o > 0; o >>= 1) {
                mA = fmaxf(mA, __shfl_xor_sync(0xffffffffu, mA, o));
                mB = fmaxf(mB, __shfl_xor_sync(0xffffffffu, mB, o));
            }
            float sAcc = 0.f, sBcc = 0.f;
            #pragma unroll
            for (int u = 0; u < 4; u++) {
                int j = lane + 32*u;
                if (j < NN) {
                    va[u] = __expf(va[u] - mA); sAcc += va[u];
                    vb[u] = __expf(vb[u] - mB); sBcc += vb[u];
                }
            }
            #pragma unroll
            for (int o = 16; o > 0; o >>= 1) {
                sAcc += __shfl_xor_sync(0xffffffffu, sAcc, o);
                sBcc += __shfl_xor_sync(0xffffffffu, sBcc, o);
            }
            float invA = 0.5f / sAcc;     // GAMMA folded
            float invB = 0.5f / sBcc;
            #pragma unroll
            for (int u = 0; u < 4; u++) {
                int j = lane + 32*u;
                if (j < NN) rowA[j] = va[u] * invA + vb[u] * invB;
            }
        }
    }
    __syncthreads();

    // ---- output: 2 warps, lane owns d4, 10 i-rows per thread, j unrolled x4 ----
    // weights read as uniform LDS.128 (float4 per row) instead of scalar broadcasts;
    // hv row read once and reused by all 10 row-accumulators.
    if (tid < 64) {
        const int lane = tid & 31;
        const int g    = tid >> 5;        // 0: rows 0-9, 1: rows 10-19
        const int d4   = lane * 4;
        float* og = out + (size_t)b * NN * DD;

        ulonglong2 acc[10];
        #pragma unroll
        for (int r = 0; r < 10; r++) acc[r].x = acc[r].y = 0ull;

        #pragma unroll 1
        for (int j = 0; j < NN; j += 4) {
            float4 wv[10];
            #pragma unroll
            for (int r = 0; r < 10; r++)
                wv[r] = *(const float4*)&sA[(g*10 + r) * NN + j];   // uniform per warp
            ulonglong2 hv[4];
            #pragma unroll
            for (int u = 0; u < 4; u++)
                hv[u] = *(const ulonglong2*)&Hs[(j+u) * PITCH + d4]; // dense 512B
            #pragma unroll
            for (int r = 0; r < 10; r++) {
                u64t t0 = dup2(wv[r].x);
                u64t t1 = dup2(wv[r].y);
                u64t t2 = dup2(wv[r].z);
                u64t t3 = dup2(wv[r].w);
                fma2(acc[r].x, t0, hv[0].x); fma2(acc[r].y, t0, hv[0].y);
                fma2(acc[r].x, t1, hv[1].x); fma2(acc[r].y, t1, hv[1].y);
                fma2(acc[r].x, t2, hv[2].x); fma2(acc[r].y, t2, hv[2].y);
                fma2(acc[r].x, t3, hv[3].x); fma2(acc[r].y, t3, hv[3].y);
            }
        }
        #pragma unroll
        for (int r = 0; r < 10; r++)
            *(ulonglong2*)&og[(i0 + g*10 + r) * DD + d4] = acc[r];
    }
}

extern "C" void kernel_launch(void* const* d_in, const int* in_sizes, int n_in,
                              void* d_out, int out_size)
{
    const float* hidden = (const float*)d_in[0];
    const int*   adj    = (const int*)  d_in[1];
    const int*   beh    = (const int*)  d_in[2];
    const float* A      = (const float*)d_in[3];
    const float* Bm     = (const float*)d_in[4];
    float*       out    = (float*)d_out;

    cudaFuncSetAttribute(la_kernel,
                         cudaFuncAttributeMaxDynamicSharedMemorySize,
                         SMEM_BYTES);

    dim3 grid(BATCH * NTILES);    // 640 CTAs
    la_kernel<<<grid, THREADS, SMEM_BYTES>>>(hidden, adj, beh, A, Bm, out);
}

// round 11
// speedup vs baseline: 1.0484x; 1.0484x over previous
#include <cuda_runtime.h>

#define BATCH   128
#define NN      100
#define DD      128
#define ITILE   10          // i-rows per CTA (100/10 = 10 tiles per batch)
#define NTILES  10
#define PITCH   132         // PITCH/4 == 33 ≡ 1 (mod 8): consecutive rows -> distinct quad-bank groups
#define THREADS 256
#define MASKV   (-9e15f)
#define NEG_BIG (-3.4e38f)

// smem (floats): Hs 100*132 | At 3*132 | Bt 9*132 | sA 10*100 | sB 10*100  = 65.6 KB
#define SMEM_FLOATS (NN*PITCH + 3*PITCH + 9*PITCH + 2*ITILE*NN)
#define SMEM_BYTES  (SMEM_FLOATS * 4)

typedef unsigned long long u64t;

// packed fp32x2 helpers (sm_100+): 2 IEEE fp32 ops per instruction
__device__ __forceinline__ u64t mul2(u64t a, u64t b) {
    u64t r;
    asm("mul.rn.f32x2 %0, %1, %2;" : "=l"(r) : "l"(a), "l"(b));
    return r;
}
__device__ __forceinline__ void fma2(u64t& acc, u64t a, u64t b) {
    asm("fma.rn.f32x2 %0, %1, %2, %0;" : "+l"(acc) : "l"(a), "l"(b));
}
__device__ __forceinline__ u64t dup2(float f) {
    u64t r;
    asm("mov.b64 %0, {%1, %1};" : "=l"(r) : "f"(f));
    return r;
}
__device__ __forceinline__ float hsum2(u64t v) {
    float lo, hi;
    asm("mov.b64 {%0, %1}, %2;" : "=f"(lo), "=f"(hi) : "l"(v));
    return lo + hi;
}

extern "C" __global__ void __launch_bounds__(THREADS, 3)
la_kernel(const float* __restrict__ hidden,
          const int*   __restrict__ adj,
          const int*   __restrict__ beh,
          const float* __restrict__ A,
          const float* __restrict__ Bm,
          float*       __restrict__ out)
{
    extern __shared__ float smem[];
    float* Hs = smem;
    float* At = Hs + NN*PITCH;
    float* Bt = At + 3*PITCH;
    float* sA = Bt + 9*PITCH;
    float* sB = sA + ITILE*NN;

    const int tid = threadIdx.x;
    const int b   = blockIdx.x / NTILES;
    const int i0  = (blockIdx.x % NTILES) * ITILE;

    // ---- stage hidden[b] (pitched, float4) ----
    {
        const float4* hg = (const float4*)(hidden + (size_t)b * NN * DD);
        for (int v = tid; v < NN * (DD/4); v += THREADS) {
            int j = v >> 5;                       // DD/4 == 32
            int qq = v & 31;
            *(float4*)&Hs[j * PITCH + qq * 4] = hg[j * (DD/4) + qq];
        }
    }
    // ---- stage A,Bm transposed ----
    for (int t = tid; t < DD*3; t += THREADS) {
        int d = t / 3, k = t - d*3;
        At[k * PITCH + d] = A[t];
    }
    for (int t = tid; t < DD*9; t += THREADS) {
        int d = t / 9, k = t - d*9;
        Bt[k * PITCH + d] = Bm[t];
    }
    __syncthreads();

    // ---- score phase: 2i x 2j per thread, dense-A (3 ch) + gathered-B, f32x2 math ----
    if (tid < 250) {
        const int p = tid / 50;                   // i-group 0..4  -> rows p, p+5
        const int q = tid - p * 50;               // j-group 0..49 -> cols q, q+50
        const int* adjB = adj + (size_t)b * NN * NN;
        const int* behB = beh + (size_t)b * NN * NN;

        unsigned iaPack = 0, vaPack = 0, vbPack = 0;
        const float* bp[2][2];
        #pragma unroll
        for (int t = 0; t < 2; t++) {
            int i = i0 + p + 5*t;
            #pragma unroll
            for (int s = 0; s < 2; s++) {
                int j  = q + 50*s;
                int ca = adjB[i * NN + j];
                int cb = behB[i * NN + j];
                int ia = min(max(ca - 1, 0), 2);
                int ib = min(max(cb - 1, 0), 8);
                int k  = t*2 + s;
                iaPack |= (unsigned)ia << (2*k);
                vaPack |= (unsigned)((ca >= 1) & (ca <= 3)) << k;
                vbPack |= (unsigned)(cb >= 1) << k;
                bp[t][s] = &Bt[ib * PITCH];
            }
        }
        const float* hiP0 = &Hs[(i0 + p)     * PITCH];
        const float* hiP1 = &Hs[(i0 + p + 5) * PITCH];

        u64t a0c[2][2], a1c[2][2], a2c[2][2], bAc[2][2];
        #pragma unroll
        for (int t = 0; t < 2; t++)
            #pragma unroll
            for (int s = 0; s < 2; s++)
                a0c[t][s] = a1c[t][s] = a2c[t][s] = bAc[t][s] = 0ull;

        #pragma unroll 1
        for (int d = 0; d < DD; d += 4) {
            ulonglong2 w0 = *(const ulonglong2*)&At[d];             // broadcast
            ulonglong2 w1 = *(const ulonglong2*)&At[PITCH   + d];
            ulonglong2 w2 = *(const ulonglong2*)&At[2*PITCH + d];
            ulonglong2 hi[2], hj[2];
            hi[0] = *(const ulonglong2*)(hiP0 + d);
            hi[1] = *(const ulonglong2*)(hiP1 + d);
            hj[0] = *(const ulonglong2*)&Hs[ q       * PITCH + d];
            hj[1] = *(const ulonglong2*)&Hs[(q + 50) * PITCH + d];
            #pragma unroll
            for (int t = 0; t < 2; t++) {
                #pragma unroll
                for (int s = 0; s < 2; s++) {
                    ulonglong2 bv = *(const ulonglong2*)(bp[t][s] + d); // gather (9 rows)
                    u64t plo = mul2(hi[t].x, hj[s].x);
                    u64t phi = mul2(hi[t].y, hj[s].y);
                    fma2(a0c[t][s], plo, w0.x); fma2(a0c[t][s], phi, w0.y);
                    fma2(a1c[t][s], plo, w1.x); fma2(a1c[t][s], phi, w1.y);
                    fma2(a2c[t][s], plo, w2.x); fma2(a2c[t][s], phi, w2.y);
                    fma2(bAc[t][s], plo, bv.x); fma2(bAc[t][s], phi, bv.y);
                }
            }
        }

        #pragma unroll
        for (int t = 0; t < 2; t++) {
            int il = p + 5*t;
            #pragma unroll
            for (int s = 0; s < 2; s++) {
                int j = q + 50*s;
                int k = t*2 + s;
                int ia = (iaPack >> (2*k)) & 3;
                u64t sel = (ia == 0) ? a0c[t][s] : (ia == 1) ? a1c[t][s] : a2c[t][s];
                float va = hsum2(sel);
                float vb = hsum2(bAc[t][s]);
                va = va >= 0.f ? va : 0.2f * va;       // LeakyReLU(0.2)
                vb = vb >= 0.f ? vb : 0.2f * vb;
                sA[il * NN + j] = ((vaPack >> k) & 1) ? va : MASKV;
                sB[il * NN + j] = ((vbPack >> k) & 1) ? vb : MASKV;
            }
        }
    }
    __syncthreads();

    // ---- dual softmax + combine: W[j] = 0.5*pA[j] + 0.5*pB[j] (into sA) ----
    {
        int w = tid >> 5, lane = tid & 31;
        for (int r = w; r < 2 * ITILE; r += THREADS/32) {
            float* rowA = (r < ITILE) ? &sA[r * NN] : &sB[(r - ITILE) * NN];
            float v[4];
            float m = NEG_BIG;
            #pragma unroll
            for (int u = 0; u < 4; u++) {
                int j = lane + 32*u;
                v[u] = (j < NN) ? rowA[j] : NEG_BIG;
                m = fmaxf(m, v[u]);
            }
            #pragma unroll
            for (int o = 16; o > 0; o >>= 1)
                m = fmaxf(m, __shfl_xor_sync(0xffffffffu, m, o));
            float s = 0.f;
            #pragma unroll
            for (int u = 0; u < 4; u++) {
                int j = lane + 32*u;
                if (j < NN) { v[u] = __expf(v[u] - m); s += v[u]; }
            }
            #pragma unroll
            for (int o = 16; o > 0; o >>= 1)
                s += __shfl_xor_sync(0xffffffffu, s, o);
            float inv = 0.5f / s;          // GAMMA folded
            #pragma unroll
            for (int u = 0; u < 4; u++) {
                int j = lane + 32*u;
                if (j < NN) rowA[j] = v[u] * inv;
            }
        }
    }
    __syncthreads();
    // combine B probs into A rows: sA += sB (separate pass keeps softmax simple)
    for (int t = tid; t < ITILE * NN; t += THREADS)
        sA[t] += sB[t];
    __syncthreads();

    // ---- output: 2 i-rows per thread (il, il+5), f32x2 math ----
    {
        float* og = out + (size_t)b * NN * DD;
        for (int o = tid; o < (ITILE/2) * (DD/4); o += THREADS) {   // 160 items
            int il = o >> 5;                  // 0..4
            int d4 = (o & 31) * 4;
            const float* w1 = &sA[ il      * NN];
            const float* w2 = &sA[(il + 5) * NN];
            ulonglong2 acc1 = {0ull, 0ull}, acc2 = {0ull, 0ull};
            #pragma unroll 2
            for (int j = 0; j < NN; j++) {
                u64t t1 = dup2(w1[j]);
                u64t t2 = dup2(w2[j]);
                ulonglong2 hv = *(const ulonglong2*)&Hs[j * PITCH + d4];
                fma2(acc1.x, t1, hv.x); fma2(acc1.y, t1, hv.y);
                fma2(acc2.x, t2, hv.x); fma2(acc2.y, t2, hv.y);
            }
            *(ulonglong2*)&og[(i0 + il)     * DD + d4] = acc1;
            *(ulonglong2*)&og[(i0 + il + 5) * DD + d4] = acc2;
        }
    }
}

extern "C" void kernel_launch(void* const* d_in, const int* in_sizes, int n_in,
                              void* d_out, int out_size)
{
    const float* hidden = (const float*)d_in[0];
    const int*   adj    = (const int*)  d_in[1];
    const int*   beh    = (const int*)  d_in[2];
    const float* A      = (const float*)d_in[3];
    const float* Bm     = (const float*)d_in[4];
    float*       out    = (float*)d_out;

    cudaFuncSetAttribute(la_kernel,
                         cudaFuncAttributeMaxDynamicSharedMemorySize,
                         SMEM_BYTES);

    dim3 grid(BATCH * NTILES);    // 1280 CTAs
    la_kernel<<<grid, THREADS, SMEM_BYTES>>>(hidden, adj, beh, A, Bm, out);
}

// round 12
// speedup vs baseline: 1.0500x; 1.0016x over previous
#include <cuda_runtime.h>

#define BATCH   128
#define NN      100
#define DD      128
#define ITILE   10          // i-rows per CTA (100/10 = 10 tiles per batch)
#define NTILES  10
#define PITCH   132         // PITCH/4 == 33 ≡ 1 (mod 8): consecutive rows -> distinct quad-bank groups
#define THREADS 256
#define MASKV   (-9e15f)
#define NEG_BIG (-3.4e38f)

// smem (floats): Hs 100*132 | At 3*132 | Bt 9*132 | sA 10*100 | sB 10*100  = 65.6 KB
#define SMEM_FLOATS (NN*PITCH + 3*PITCH + 9*PITCH + 2*ITILE*NN)
#define SMEM_BYTES  (SMEM_FLOATS * 4)

typedef unsigned long long u64t;

// packed fp32x2 helpers (sm_100+): 2 IEEE fp32 ops per instruction
__device__ __forceinline__ u64t mul2(u64t a, u64t b) {
    u64t r;
    asm("mul.rn.f32x2 %0, %1, %2;" : "=l"(r) : "l"(a), "l"(b));
    return r;
}
__device__ __forceinline__ void fma2(u64t& acc, u64t a, u64t b) {
    asm("fma.rn.f32x2 %0, %1, %2, %0;" : "+l"(acc) : "l"(a), "l"(b));
}
__device__ __forceinline__ float hsum2(u64t v) {
    float lo, hi;
    asm("mov.b64 {%0, %1}, %2;" : "=f"(lo), "=f"(hi) : "l"(v));
    return lo + hi;
}

extern "C" __global__ void __launch_bounds__(THREADS, 3)
la_kernel(const float* __restrict__ hidden,
          const int*   __restrict__ adj,
          const int*   __restrict__ beh,
          const float* __restrict__ A,
          const float* __restrict__ Bm,
          float*       __restrict__ out)
{
    extern __shared__ float smem[];
    float* Hs = smem;
    float* At = Hs + NN*PITCH;
    float* Bt = At + 3*PITCH;
    float* sA = Bt + 9*PITCH;
    float* sB = sA + ITILE*NN;

    const int tid = threadIdx.x;
    const int b   = blockIdx.x / NTILES;
    const int i0  = (blockIdx.x % NTILES) * ITILE;

    // ---- stage hidden[b] (pitched, float4) ----
    {
        const float4* hg = (const float4*)(hidden + (size_t)b * NN * DD);
        for (int v = tid; v < NN * (DD/4); v += THREADS) {
            int j = v >> 5;                       // DD/4 == 32
            int qq = v & 31;
            *(float4*)&Hs[j * PITCH + qq * 4] = hg[j * (DD/4) + qq];
        }
    }
    // ---- stage A,Bm transposed ----
    for (int t = tid; t < DD*3; t += THREADS) {
        int d = t / 3, k = t - d*3;
        At[k * PITCH + d] = A[t];
    }
    for (int t = tid; t < DD*9; t += THREADS) {
        int d = t / 9, k = t - d*9;
        Bt[k * PITCH + d] = Bm[t];
    }
    __syncthreads();

    // ---- score phase: 2i x 2j per thread, dense-A (3 ch) + gathered-B, f32x2 math ----
    // (byte-identical to R10 best)
    if (tid < 250) {
        const int p = tid / 50;                   // i-group 0..4  -> rows p, p+5
        const int q = tid - p * 50;               // j-group 0..49 -> cols q, q+50
        const int* adjB = adj + (size_t)b * NN * NN;
        const int* behB = beh + (size_t)b * NN * NN;

        unsigned iaPack = 0, vaPack = 0, vbPack = 0;
        const float* bp[2][2];
        #pragma unroll
        for (int t = 0; t < 2; t++) {
            int i = i0 + p + 5*t;
            #pragma unroll
            for (int s = 0; s < 2; s++) {
                int j  = q + 50*s;
                int ca = adjB[i * NN + j];
                int cb = behB[i * NN + j];
                int ia = min(max(ca - 1, 0), 2);
                int ib = min(max(cb - 1, 0), 8);
                int k  = t*2 + s;
                iaPack |= (unsigned)ia << (2*k);
                vaPack |= (unsigned)((ca >= 1) & (ca <= 3)) << k;
                vbPack |= (unsigned)(cb >= 1) << k;
                bp[t][s] = &Bt[ib * PITCH];
            }
        }
        const float* hiP0 = &Hs[(i0 + p)     * PITCH];
        const float* hiP1 = &Hs[(i0 + p + 5) * PITCH];

        u64t a0c[2][2], a1c[2][2], a2c[2][2], bAc[2][2];
        #pragma unroll
        for (int t = 0; t < 2; t++)
            #pragma unroll
            for (int s = 0; s < 2; s++)
                a0c[t][s] = a1c[t][s] = a2c[t][s] = bAc[t][s] = 0ull;

        #pragma unroll 1
        for (int d = 0; d < DD; d += 4) {
            ulonglong2 w0 = *(const ulonglong2*)&At[d];             // broadcast
            ulonglong2 w1 = *(const ulonglong2*)&At[PITCH   + d];
            ulonglong2 w2 = *(const ulonglong2*)&At[2*PITCH + d];
            ulonglong2 hi[2], hj[2];
            hi[0] = *(const ulonglong2*)(hiP0 + d);
            hi[1] = *(const ulonglong2*)(hiP1 + d);
            hj[0] = *(const ulonglong2*)&Hs[ q       * PITCH + d];
            hj[1] = *(const ulonglong2*)&Hs[(q + 50) * PITCH + d];
            #pragma unroll
            for (int t = 0; t < 2; t++) {
                #pragma unroll
                for (int s = 0; s < 2; s++) {
                    ulonglong2 bv = *(const ulonglong2*)(bp[t][s] + d); // gather (9 rows)
                    u64t plo = mul2(hi[t].x, hj[s].x);
                    u64t phi = mul2(hi[t].y, hj[s].y);
                    fma2(a0c[t][s], plo, w0.x); fma2(a0c[t][s], phi, w0.y);
                    fma2(a1c[t][s], plo, w1.x); fma2(a1c[t][s], phi, w1.y);
                    fma2(a2c[t][s], plo, w2.x); fma2(a2c[t][s], phi, w2.y);
                    fma2(bAc[t][s], plo, bv.x); fma2(bAc[t][s], phi, bv.y);
                }
            }
        }

        #pragma unroll
        for (int t = 0; t < 2; t++) {
            int il = p + 5*t;
            #pragma unroll
            for (int s = 0; s < 2; s++) {
                int j = q + 50*s;
                int k = t*2 + s;
                int ia = (iaPack >> (2*k)) & 3;
                u64t sel = (ia == 0) ? a0c[t][s] : (ia == 1) ? a1c[t][s] : a2c[t][s];
                float va = hsum2(sel);
                float vb = hsum2(bAc[t][s]);
                va = va >= 0.f ? va : 0.2f * va;       // LeakyReLU(0.2)
                vb = vb >= 0.f ? vb : 0.2f * vb;
                sA[il * NN + j] = ((vaPack >> k) & 1) ? va : MASKV;
                sB[il * NN + j] = ((vbPack >> k) & 1) ? vb : MASKV;
            }
        }
    }
    __syncthreads();

    // ---- dual softmax + combine: sA[row] = 0.5*softmax(sA) + 0.5*softmax(sB) ----
    {
        int w = tid >> 5, lane = tid & 31;
        for (int r = w; r < ITILE; r += THREADS/32) {
            float* rowA = &sA[r * NN];
            float* rowB = &sB[r * NN];
            float va[4], vb[4];
            float mA = NEG_BIG, mB = NEG_BIG;
            #pragma unroll
            for (int u = 0; u < 4; u++) {
                int j = lane + 32*u;
                va[u] = (j < NN) ? rowA[j] : NEG_BIG;
                vb[u] = (j < NN) ? rowB[j] : NEG_BIG;
                mA = fmaxf(mA, va[u]);
                mB = fmaxf(mB, vb[u]);
            }
            #pragma unroll
            for (int o = 16; o > 0; o >>= 1) {
                mA = fmaxf(mA, __shfl_xor_sync(0xffffffffu, mA, o));
                mB = fmaxf(mB, __shfl_xor_sync(0xffffffffu, mB, o));
            }
            float sAcc = 0.f, sBcc = 0.f;
            #pragma unroll
            for (int u = 0; u < 4; u++) {
                int j = lane + 32*u;
                if (j < NN) {
                    va[u] = __expf(va[u] - mA); sAcc += va[u];
                    vb[u] = __expf(vb[u] - mB); sBcc += vb[u];
                }
            }
            #pragma unroll
            for (int o = 16; o > 0; o >>= 1) {
                sAcc += __shfl_xor_sync(0xffffffffu, sAcc, o);
                sBcc += __shfl_xor_sync(0xffffffffu, sBcc, o);
            }
            float invA = 0.5f / sAcc;     // GAMMA folded
            float invB = 0.5f / sBcc;
            #pragma unroll
            for (int u = 0; u < 4; u++) {
                int j = lane + 32*u;
                if (j < NN) rowA[j] = va[u] * invA + vb[u] * invB;
            }
        }
    }
    __syncthreads();

    // ---- output: 2 i-rows per thread (il, il+5); j unrolled x4 with uniform
    //      float4 weight loads (1-cyc broadcast) instead of per-j scalars ----
    {
        float* og = out + (size_t)b * NN * DD;
        for (int o = tid; o < (ITILE/2) * (DD/4); o += THREADS) {   // 160 items
            int il = o >> 5;                  // 0..4 (uniform per warp)
            int d4 = (o & 31) * 4;
            const float* w1 = &sA[ il      * NN];
            const float* w2 = &sA[(il + 5) * NN];
            float4 acc1 = make_float4(0.f,0.f,0.f,0.f);
            float4 acc2 = make_float4(0.f,0.f,0.f,0.f);
            #pragma unroll 1
            for (int j = 0; j < NN; j += 4) {
                float4 wv1 = *(const float4*)&w1[j];     // uniform per warp
                float4 wv2 = *(const float4*)&w2[j];     // uniform per warp
                float4 hv0 = *(const float4*)&Hs[(j+0) * PITCH + d4];
                float4 hv1 = *(const float4*)&Hs[(j+1) * PITCH + d4];
                float4 hv2 = *(const float4*)&Hs[(j+2) * PITCH + d4];
                float4 hv3 = *(const float4*)&Hs[(j+3) * PITCH + d4];
                acc1.x = fmaf(wv1.x, hv0.x, acc1.x);
                acc1.y = fmaf(wv1.x, hv0.y, acc1.y);
                acc1.z = fmaf(wv1.x, hv0.z, acc1.z);
                acc1.w = fmaf(wv1.x, hv0.w, acc1.w);
                acc2.x = fmaf(wv2.x, hv0.x, acc2.x);
                acc2.y = fmaf(wv2.x, hv0.y, acc2.y);
                acc2.z = fmaf(wv2.x, hv0.z, acc2.z);
                acc2.w = fmaf(wv2.x, hv0.w, acc2.w);
                acc1.x = fmaf(wv1.y, hv1.x, acc1.x);
                acc1.y = fmaf(wv1.y, hv1.y, acc1.y);
                acc1.z = fmaf(wv1.y, hv1.z, acc1.z);
                acc1.w = fmaf(wv1.y, hv1.w, acc1.w);
                acc2.x = fmaf(wv2.y, hv1.x, acc2.x);
                acc2.y = fmaf(wv2.y, hv1.y, acc2.y);
                acc2.z = fmaf(wv2.y, hv1.z, acc2.z);
                acc2.w = fmaf(wv2.y, hv1.w, acc2.w);
                acc1.x = fmaf(wv1.z, hv2.x, acc1.x);
                acc1.y = fmaf(wv1.z, hv2.y, acc1.y);
                acc1.z = fmaf(wv1.z, hv2.z, acc1.z);
                acc1.w = fmaf(wv1.z, hv2.w, acc1.w);
                acc2.x = fmaf(wv2.z, hv2.x, acc2.x);
                acc2.y = fmaf(wv2.z, hv2.y, acc2.y);
                acc2.z = fmaf(wv2.z, hv2.z, acc2.z);
                acc2.w = fmaf(wv2.z, hv2.w, acc2.w);
                acc1.x = fmaf(wv1.w, hv3.x, acc1.x);
                acc1.y = fmaf(wv1.w, hv3.y, acc1.y);
                acc1.z = fmaf(wv1.w, hv3.z, acc1.z);
                acc1.w = fmaf(wv1.w, hv3.w, acc1.w);
                acc2.x = fmaf(wv2.w, hv3.x, acc2.x);
                acc2.y = fmaf(wv2.w, hv3.y, acc2.y);
                acc2.z = fmaf(wv2.w, hv3.z, acc2.z);
                acc2.w = fmaf(wv2.w, hv3.w, acc2.w);
            }
            *(float4*)&og[(i0 + il)     * DD + d4] = acc1;
            *(float4*)&og[(i0 + il + 5) * DD + d4] = acc2;
        }
    }
}

extern "C" void kernel_launch(void* const* d_in, const int* in_sizes, int n_in,
                              void* d_out, int out_size)
{
    const float* hidden = (const float*)d_in[0];
    const int*   adj    = (const int*)  d_in[1];
    const int*   beh    = (const int*)  d_in[2];
    const float* A      = (const float*)d_in[3];
    const float* Bm     = (const float*)d_in[4];
    float*       out    = (float*)d_out;

    cudaFuncSetAttribute(la_kernel,
                         cudaFuncAttributeMaxDynamicSharedMemorySize,
                         SMEM_BYTES);

    dim3 grid(BATCH * NTILES);    // 1280 CTAs
    la_kernel<<<grid, THREADS, SMEM_BYTES>>>(hidden, adj, beh, A, Bm, out);
}